// round 2
// baseline (speedup 1.0000x reference)
#include <cuda_runtime.h>
#include <math.h>

#define NN 10000
#define EE 160000
#define ET (EE + NN)
#define HH 8
#define DD 128
#define HD 1024   // H*D

// ---------------- scratch (static device allocations; no cudaMalloc) --------
__device__ int   d_is64;
__device__ int   d_deg[NN];
__device__ int   d_cursor[NN];
__device__ int   d_rowptr[NN + 1];
__device__ int   d_colsrc[ET];
__device__ __align__(16) float d_as[NN * HH];
__device__ __align__(16) float d_ad[NN * HH];
__device__ __align__(16) float d_dinv[NN];
__device__ __align__(16) float d_snode[NN * 32];   // [N][H][4]
__device__ __align__(16) float d_g[NN * HD];       // gelu(GAT out) [N,1024]
__device__ __align__(16) float d_t1[NN * DD];
__device__ __align__(16) float d_h1[NN * DD];
__device__ __align__(16) float d_t2[NN * DD];
__device__ __align__(16) float d_csrc[32];         // [H][4]
__device__ __align__(16) float d_cdst[32];

// ---------------- helpers ---------------------------------------------------
__device__ __forceinline__ float gelu_exact(float v) {
    return 0.5f * v * (1.0f + erff(v * 0.70710678118654752440f));
}

__device__ __forceinline__ unsigned long long fma2(unsigned long long a,
                                                   unsigned long long b,
                                                   unsigned long long c) {
    unsigned long long d;
    asm("fma.rn.f32x2 %0, %1, %2, %3;" : "=l"(d) : "l"(a), "l"(b), "l"(c));
    return d;
}
__device__ __forceinline__ unsigned long long pack2(float x, float y) {
    unsigned long long r;
    asm("mov.b64 %0, {%1, %2};" : "=l"(r) : "f"(x), "f"(y));
    return r;
}
__device__ __forceinline__ void unpack2(unsigned long long v, float& x, float& y) {
    asm("mov.b64 {%0, %1}, %2;" : "=f"(x), "=f"(y) : "l"(v));
}

// ---------------- dtype detection for edge_index ----------------------------
// int64 little-endian values < 2^31 have all-zero odd 32-bit words.
__global__ void k_detect(const int* __restrict__ w) {
    __shared__ int nz;
    if (threadIdx.x == 0) nz = 0;
    __syncthreads();
    if (w[2 * threadIdx.x + 1] != 0) atomicOr(&nz, 1);
    __syncthreads();
    if (threadIdx.x == 0) d_is64 = nz ? 0 : 1;
}

// ---------------- prep: c_src/c_dst = gat_w^T @ att (rank-4 collapse) -------
__global__ void k_prep_c(const float* __restrict__ gw,
                         const float* __restrict__ asrc,
                         const float* __restrict__ adst) {
    int t = threadIdx.x;
    if (t >= 64) return;
    int which = t >> 5;            // 0: src, 1: dst
    int idx = t & 31;              // h*4+f
    int h = idx >> 2, f = idx & 3;
    const float* att = which ? adst : asrc;
    float s = 0.0f;
    for (int d = 0; d < DD; d++)
        s += gw[f * HD + h * DD + d] * att[h * DD + d];
    if (which) d_cdst[idx] = s; else d_csrc[idx] = s;
}

// ---------------- CSR build -------------------------------------------------
__global__ void k_init() {
    int i = blockIdx.x * blockDim.x + threadIdx.x;
    if (i < NN) { d_deg[i] = 1; d_cursor[i] = 0; }   // deg starts at 1 (self loop)
}

__global__ void k_count(const int* __restrict__ w) {
    int e = blockIdx.x * blockDim.x + threadIdx.x;
    if (e >= EE) return;
    int is64 = d_is64;
    int dd = is64 ? w[2 * (EE + e)] : w[EE + e];
    if ((unsigned)dd < NN) atomicAdd(&d_deg[dd], 1);
}

__global__ void k_scan() {   // 1 block, 1024 threads
    __shared__ int sh[1024];
    int t = threadIdx.x;
    const int C = 10;                 // 1024*10 >= 10000
    int base = t * C;
    int sum = 0;
    for (int i = 0; i < C; i++) {
        int idx = base + i;
        if (idx < NN) sum += d_deg[idx];
    }
    sh[t] = sum;
    __syncthreads();
    for (int off = 1; off < 1024; off <<= 1) {
        int v = 0;
        if (t >= off) v = sh[t - off];
        __syncthreads();
        if (t >= off) sh[t] += v;
        __syncthreads();
    }
    int run = sh[t] - sum;            // exclusive prefix
    for (int i = 0; i < C; i++) {
        int idx = base + i;
        if (idx < NN) { d_rowptr[idx] = run; run += d_deg[idx]; }
    }
    if (t == 1023) d_rowptr[NN] = sh[1023];
}

__global__ void k_fill(const int* __restrict__ w) {
    int t = blockIdx.x * blockDim.x + threadIdx.x;
    if (t >= ET) return;
    int is64 = d_is64;
    int s, dd;
    if (t < EE) {
        s  = is64 ? w[2 * t]          : w[t];
        dd = is64 ? w[2 * (EE + t)]   : w[EE + t];
    } else {
        s = t - EE; dd = s;           // self loop
    }
    if ((unsigned)dd >= NN || (unsigned)s >= NN) return;
    int pos = atomicAdd(&d_cursor[dd], 1);
    d_colsrc[d_rowptr[dd] + pos] = s;
}

// ---------------- per-node: attention scores + dinv -------------------------
__global__ void k_node(const float* __restrict__ x) {
    int n = blockIdx.x * blockDim.x + threadIdx.x;
    if (n >= NN) return;
    float4 xv = ((const float4*)x)[n];
#pragma unroll
    for (int h = 0; h < HH; h++) {
        d_as[n * 8 + h] = xv.x * d_csrc[h * 4 + 0] + xv.y * d_csrc[h * 4 + 1]
                        + xv.z * d_csrc[h * 4 + 2] + xv.w * d_csrc[h * 4 + 3];
        d_ad[n * 8 + h] = xv.x * d_cdst[h * 4 + 0] + xv.y * d_cdst[h * 4 + 1]
                        + xv.z * d_cdst[h * 4 + 2] + xv.w * d_cdst[h * 4 + 3];
    }
    d_dinv[n] = rsqrtf((float)d_deg[n]);
}

// ---------------- GAT softmax + rank-4 aggregation (lane = head) ------------
__global__ void k_gat(const float* __restrict__ x) {
    int node = blockIdx.x * 32 + (threadIdx.x >> 3);   // 32 nodes per block
    int h = threadIdx.x & 7;
    if (node >= NN) return;
    int r0 = d_rowptr[node], r1 = d_rowptr[node + 1];
    float ad = d_ad[node * 8 + h];
    float m = -1e30f;
    for (int i = r0; i < r1; i++) {
        int s = d_colsrc[i];
        float e = d_as[s * 8 + h] + ad;
        e = e > 0.0f ? e : 0.2f * e;
        m = fmaxf(m, e);
    }
    float den = 0.0f, t0 = 0.0f, t1 = 0.0f, t2 = 0.0f, t3 = 0.0f;
    for (int i = r0; i < r1; i++) {
        int s = d_colsrc[i];
        float e = d_as[s * 8 + h] + ad;
        e = e > 0.0f ? e : 0.2f * e;
        float ex = expf(e - m);
        den += ex;
        float4 xv = ((const float4*)x)[s];
        t0 += ex * xv.x; t1 += ex * xv.y; t2 += ex * xv.z; t3 += ex * xv.w;
    }
    float inv = 1.0f / den;
    float* sp = &d_snode[node * 32 + h * 4];
    sp[0] = t0 * inv; sp[1] = t1 * inv; sp[2] = t2 * inv; sp[3] = t3 * inv;
}

// ---------------- g = gelu(s @ gat_w + gat_b) --------------------------------
__global__ void k_g(const float* __restrict__ gw, const float* __restrict__ gb) {
    int idx = blockIdx.x * blockDim.x + threadIdx.x;
    if (idx >= NN * HD) return;
    int j = idx & (HD - 1);
    int n = idx >> 10;
    const float* sp = &d_snode[n * 32 + (j >> 7) * 4];
    float acc = gb[j];
    acc += sp[0] * gw[j] + sp[1] * gw[HD + j] + sp[2] * gw[2 * HD + j] + sp[3] * gw[3 * HD + j];
    d_g[idx] = gelu_exact(acc);
}

// ---------------- fp32x2 tiled GEMM: C[M,128] = A[M,K] @ B[K,128] -----------
// BM=64, BN=128, BK=16, 256 threads, TM=8, TN=4 (as 2x f32x2 pairs)
#define ROWFMA(r, ax) { unsigned long long _ad = pack2((ax), (ax)); \
    acc[r][0] = fma2(_ad, b01, acc[r][0]); acc[r][1] = fma2(_ad, b23, acc[r][1]); }

template <int K, int WHICH>
__global__ __launch_bounds__(256, 2) void gemm_kernel(const float* __restrict__ B, int M) {
    const float* A = (WHICH == 0) ? d_g : d_h1;
    float* C       = (WHICH == 0) ? d_t1 : d_t2;

    __shared__ float As[2][16][64];
    __shared__ float Bs[2][16][128];

    int t = threadIdx.x;
    int bm = blockIdx.x * 64;
    int row0 = (t >> 5) * 8;          // 8 rows per thread (warp-uniform)
    int col0 = (t & 31) * 4;          // 4 cols per thread

    int arow = t >> 2;                // A tile: 64 rows x 16 cols
    int acol = (t & 3) * 4;
    int brow = t >> 5;                // B tile: 16 rows x 128 cols
    int bcol = (t & 31) * 4;

    const int nk = K / 16;
    float4 aReg, bReg0, bReg1;

    // load tile 0
    {
        int m = bm + arow;
        aReg = (m < M) ? *(const float4*)(A + (size_t)m * K + acol)
                       : make_float4(0.f, 0.f, 0.f, 0.f);
        bReg0 = *(const float4*)(B + brow * 128 + bcol);
        bReg1 = *(const float4*)(B + (brow + 8) * 128 + bcol);
        As[0][acol + 0][arow] = aReg.x;
        As[0][acol + 1][arow] = aReg.y;
        As[0][acol + 2][arow] = aReg.z;
        As[0][acol + 3][arow] = aReg.w;
        *(float4*)&Bs[0][brow][bcol] = bReg0;
        *(float4*)&Bs[0][brow + 8][bcol] = bReg1;
    }
    __syncthreads();

    unsigned long long acc[8][2];
#pragma unroll
    for (int r = 0; r < 8; r++) { acc[r][0] = 0ULL; acc[r][1] = 0ULL; }

    for (int kt = 0; kt < nk; kt++) {
        int cur = kt & 1;
        if (kt + 1 < nk) {
            int k0 = (kt + 1) * 16;
            int m = bm + arow;
            aReg = (m < M) ? *(const float4*)(A + (size_t)m * K + k0 + acol)
                           : make_float4(0.f, 0.f, 0.f, 0.f);
            bReg0 = *(const float4*)(B + (k0 + brow) * 128 + bcol);
            bReg1 = *(const float4*)(B + (k0 + brow + 8) * 128 + bcol);
        }
#pragma unroll
        for (int k = 0; k < 16; k++) {
            float4 a0 = *(const float4*)&As[cur][k][row0];
            float4 a1 = *(const float4*)&As[cur][k][row0 + 4];
            float4 bv = *(const float4*)&Bs[cur][k][col0];
            unsigned long long b01 = pack2(bv.x, bv.y);
            unsigned long long b23 = pack2(bv.z, bv.w);
            ROWFMA(0, a0.x) ROWFMA(1, a0.y) ROWFMA(2, a0.z) ROWFMA(3, a0.w)
            ROWFMA(4, a1.x) ROWFMA(5, a1.y) ROWFMA(6, a1.z) ROWFMA(7, a1.w)
        }
        if (kt + 1 < nk) {
            int nxt = cur ^ 1;
            As[nxt][acol + 0][arow] = aReg.x;
            As[nxt][acol + 1][arow] = aReg.y;
            As[nxt][acol + 2][arow] = aReg.z;
            As[nxt][acol + 3][arow] = aReg.w;
            *(float4*)&Bs[nxt][brow][bcol] = bReg0;
            *(float4*)&Bs[nxt][brow + 8][bcol] = bReg1;
            __syncthreads();
        }
    }

#pragma unroll
    for (int r = 0; r < 8; r++) {
        int m = bm + row0 + r;
        if (m < M) {
            float4 o;
            unpack2(acc[r][0], o.x, o.y);
            unpack2(acc[r][1], o.z, o.w);
            *(float4*)&C[m * 128 + col0] = o;
        }
    }
}

// ---------------- GCN aggregation: out[n] = (opt gelu)(dinv[n]*Σ dinv[s]*t[s] + b)
template <bool GELU, bool FIRST>
__global__ void k_agg(const float* __restrict__ bias, float* __restrict__ ext_out) {
    const float* tin = FIRST ? d_t1 : d_t2;
    float*       outp = FIRST ? d_h1 : ext_out;
    int node = blockIdx.x * 8 + (threadIdx.x >> 5);
    int lane = threadIdx.x & 31;
    if (node >= NN) return;
    int r0 = d_rowptr[node], r1 = d_rowptr[node + 1];
    float4 acc = make_float4(0.f, 0.f, 0.f, 0.f);
    const float4* t4 = (const float4*)tin;
    for (int i = r0; i < r1; i++) {
        int s = d_colsrc[i];
        float w = d_dinv[s];
        float4 v = t4[s * 32 + lane];
        acc.x += w * v.x; acc.y += w * v.y; acc.z += w * v.z; acc.w += w * v.w;
    }
    float dn = d_dinv[node];
    float4 b = ((const float4*)bias)[lane];
    float4 r;
    r.x = acc.x * dn + b.x;
    r.y = acc.y * dn + b.y;
    r.z = acc.z * dn + b.z;
    r.w = acc.w * dn + b.w;
    if (GELU) {
        r.x = gelu_exact(r.x); r.y = gelu_exact(r.y);
        r.z = gelu_exact(r.z); r.w = gelu_exact(r.w);
    }
    ((float4*)outp)[node * 32 + lane] = r;
}

// ---------------- launch -----------------------------------------------------
extern "C" void kernel_launch(void* const* d_in, const int* in_sizes, int n_in,
                              void* d_out, int out_size) {
    const float* x       = (const float*)d_in[0];
    const int*   eiw     = (const int*)d_in[1];      // words; dtype detected on device
    const float* gat_w   = (const float*)d_in[2];
    const float* att_src = (const float*)d_in[3];
    const float* att_dst = (const float*)d_in[4];
    const float* gat_b   = (const float*)d_in[5];
    const float* w1      = (const float*)d_in[6];
    const float* b1      = (const float*)d_in[7];
    const float* w2      = (const float*)d_in[8];
    const float* b2      = (const float*)d_in[9];
    float* out = (float*)d_out;

    k_detect<<<1, 128>>>(eiw);
    k_prep_c<<<1, 64>>>(gat_w, att_src, att_dst);
    k_init<<<(NN + 255) / 256, 256>>>();
    k_count<<<(EE + 255) / 256, 256>>>(eiw);
    k_scan<<<1, 1024>>>();
    k_fill<<<(ET + 255) / 256, 256>>>(eiw);
    k_node<<<(NN + 255) / 256, 256>>>(x);
    k_gat<<<(NN + 31) / 32, 256>>>(x);
    k_g<<<(NN * HD + 255) / 256, 256>>>(gat_w, gat_b);
    gemm_kernel<HD, 0><<<(NN + 63) / 64, 256>>>(w1, NN);
    k_agg<true, true><<<(NN + 7) / 8, 256>>>(b1, nullptr);
    gemm_kernel<DD, 1><<<(NN + 63) / 64, 256>>>(w2, NN);
    k_agg<false, false><<<(NN + 7) / 8, 256>>>(b2, out);
}